// round 1
// baseline (speedup 1.0000x reference)
#include <cuda_runtime.h>
#include <math.h>

// Problem constants
#define BB   4
#define SS   4096
#define DMM  1024
#define DHH  1024
#define MMT  (BB*SS)      // 16384 rows
#define N1   (3*DHH)      // 3072
#define KK   1024

#define NCHUNK 32
#define TCH    (SS/NCHUNK)   // 128

// Scratch (device globals: allocation-free, graph-safe)
__device__ float g_tinp[(size_t)MMT*DHH];   // tanh(u0)
__device__ float g_gin [(size_t)MMT*DHH];   // sigmoid(u1) = input gate
__device__ float g_gout[(size_t)MMT*DHH];   // sigmoid(u2) = output gate
__device__ float g_ypre[(size_t)MMT*DHH];   // tanh(h)*og  (input to GEMM2)
__device__ float g_Ac [(size_t)BB*NCHUNK*DHH];
__device__ float g_Kc [(size_t)BB*NCHUNK*DHH];
__device__ float g_pref[(size_t)BB*NCHUNK*DHH];

// ---------------------------------------------------------------------------
// Tiled fp32 GEMM: C[M,NN] = A[M,1024] * B[1024,NN] (+bias)
// BM=BN=128, BK=16, 256 threads, 8x8 per-thread tile.
// MODE 0: GEMM1 epilogue -> split activations into g_tinp/g_gin/g_gout
// MODE 1: GEMM2 epilogue -> C = acc + bias, A source is g_ypre
// ---------------------------------------------------------------------------
template<int NN, int MODE>
__global__ __launch_bounds__(256)
void gemm_kernel(const float* __restrict__ Ain,
                 const float* __restrict__ Bmat,
                 const float* __restrict__ bias,
                 float* __restrict__ Cout)
{
    __shared__ float As[16][132];   // [k][m], padded
    __shared__ float Bs[16][132];   // [k][n], padded

    const float* A = (MODE == 1) ? g_ypre : Ain;

    const int tid = threadIdx.x;
    const int tx  = tid & 15;       // 0..15 -> N
    const int ty  = tid >> 4;       // 0..15 -> M
    const int n0  = blockIdx.x * 128;
    const int m0  = blockIdx.y * 128;

    float acc[8][8];
#pragma unroll
    for (int i = 0; i < 8; i++)
#pragma unroll
        for (int j = 0; j < 8; j++) acc[i][j] = 0.f;

    for (int k0 = 0; k0 < KK; k0 += 16) {
        // Load A tile: 128 rows x 16 cols = 512 float4
#pragma unroll
        for (int it = 0; it < 2; it++) {
            int idx = tid + it * 256;
            int row = idx >> 2;          // 0..127
            int cv  = idx & 3;           // 0..3 (float4 within the 16-wide row)
            float4 v = *reinterpret_cast<const float4*>(
                &A[(size_t)(m0 + row) * KK + k0 + cv * 4]);
            As[cv * 4 + 0][row] = v.x;
            As[cv * 4 + 1][row] = v.y;
            As[cv * 4 + 2][row] = v.z;
            As[cv * 4 + 3][row] = v.w;
        }
        // Load B tile: 16 rows x 128 cols = 512 float4
#pragma unroll
        for (int it = 0; it < 2; it++) {
            int idx = tid + it * 256;
            int row = idx >> 5;          // 0..15
            int cv  = idx & 31;          // 0..31
            float4 v = *reinterpret_cast<const float4*>(
                &Bmat[(size_t)(k0 + row) * NN + n0 + cv * 4]);
            *reinterpret_cast<float4*>(&Bs[row][cv * 4]) = v;
        }
        __syncthreads();

#pragma unroll
        for (int k = 0; k < 16; k++) {
            float a[8], b[8];
            *reinterpret_cast<float4*>(a)     = *reinterpret_cast<const float4*>(&As[k][ty * 4]);
            *reinterpret_cast<float4*>(a + 4) = *reinterpret_cast<const float4*>(&As[k][64 + ty * 4]);
            *reinterpret_cast<float4*>(b)     = *reinterpret_cast<const float4*>(&Bs[k][tx * 4]);
            *reinterpret_cast<float4*>(b + 4) = *reinterpret_cast<const float4*>(&Bs[k][64 + tx * 4]);
#pragma unroll
            for (int i = 0; i < 8; i++)
#pragma unroll
                for (int j = 0; j < 8; j++)
                    acc[i][j] = fmaf(a[i], b[j], acc[i][j]);
        }
        __syncthreads();
    }

    // Epilogue
#pragma unroll
    for (int i = 0; i < 8; i++) {
        int m = m0 + ((i < 4) ? (ty * 4 + i) : (64 + ty * 4 + (i - 4)));
#pragma unroll
        for (int j = 0; j < 8; j++) {
            int n = n0 + ((j < 4) ? (tx * 4 + j) : (64 + tx * 4 + (j - 4)));
            float u = acc[i][j] + bias[n];
            if (MODE == 0) {
                int r = n >> 10;        // which third of the 3072 columns
                int c = n & 1023;
                size_t o = (size_t)m * DHH + c;
                if (r == 0)      g_tinp[o] = tanhf(u);
                else if (r == 1) g_gin[o]  = 1.f / (1.f + expf(-u));
                else             g_gout[o] = 1.f / (1.f + expf(-u));
            } else {
                Cout[(size_t)m * NN + n] = u;
            }
        }
    }
}

// ---------------------------------------------------------------------------
// Scan pass 1: per-chunk aggregates (A = prod f, Kv = local scan end value)
// ---------------------------------------------------------------------------
__global__ __launch_bounds__(256)
void scan_pass1()
{
    int c     = blockIdx.x * blockDim.x + threadIdx.x;   // channel 0..1023
    int chunk = blockIdx.y;
    int b     = blockIdx.z;
    size_t base = ((size_t)b * SS + (size_t)chunk * TCH) * DHH + c;

    float A = 1.f, Kv = 0.f;
#pragma unroll 4
    for (int t = 0; t < TCH; t++) {
        size_t idx = base + (size_t)t * DHH;
        float gi = g_gin[idx];
        float ti = g_tinp[idx];
        float f  = 1.f - gi;
        Kv = fmaf(f, Kv, ti * gi);
        A *= f;
    }
    size_t o = ((size_t)b * NCHUNK + chunk) * DHH + c;
    g_Ac[o] = A;
    g_Kc[o] = Kv;
}

// ---------------------------------------------------------------------------
// Scan pass 2: sequential scan over chunk aggregates per (b, c)
// ---------------------------------------------------------------------------
__global__ __launch_bounds__(256)
void scan_pass2()
{
    int c = blockIdx.x * blockDim.x + threadIdx.x;
    int b = blockIdx.y;
    float carry = 0.f;
#pragma unroll
    for (int j = 0; j < NCHUNK; j++) {
        size_t o = ((size_t)b * NCHUNK + j) * DHH + c;
        g_pref[o] = carry;
        carry = fmaf(g_Ac[o], carry, g_Kc[o]);
    }
}

// ---------------------------------------------------------------------------
// Scan pass 3: replay each chunk with its global prefix; emit y_pre and h_last
// ---------------------------------------------------------------------------
__global__ __launch_bounds__(256)
void scan_pass3(float* __restrict__ hlast)
{
    int c     = blockIdx.x * blockDim.x + threadIdx.x;
    int chunk = blockIdx.y;
    int b     = blockIdx.z;

    float h = g_pref[((size_t)b * NCHUNK + chunk) * DHH + c];
    size_t base = ((size_t)b * SS + (size_t)chunk * TCH) * DHH + c;

#pragma unroll 4
    for (int t = 0; t < TCH; t++) {
        size_t idx = base + (size_t)t * DHH;
        float gi = g_gin[idx];
        float ti = g_tinp[idx];
        float f  = 1.f - gi;
        h = fmaf(f, h, ti * gi);
        g_ypre[idx] = tanhf(h) * g_gout[idx];
    }
    if (chunk == NCHUNK - 1)
        hlast[(size_t)b * DHH + c] = h;
}

// ---------------------------------------------------------------------------
extern "C" void kernel_launch(void* const* d_in, const int* in_sizes, int n_in,
                              void* d_out, int out_size)
{
    const float* x  = (const float*)d_in[0];   // (4,4096,1024)
    const float* Wp = (const float*)d_in[1];   // (1024,3072)
    const float* bp = (const float*)d_in[2];   // (3072,)
    const float* Wo = (const float*)d_in[3];   // (1024,1024)
    const float* bo = (const float*)d_in[4];   // (1024,)

    float* out   = (float*)d_out;
    float* hlast = out;                         // (4,1024) = 4096 floats
    float* y     = out + (size_t)BB * DHH;      // (4,4096,1024)

    // GEMM1: u = x @ Wp + bp, fused activation split
    gemm_kernel<N1, 0><<<dim3(N1 / 128, MMT / 128), 256>>>(x, Wp, bp, nullptr);

    // Chunked linear-recurrence scan
    scan_pass1<<<dim3(DHH / 256, NCHUNK, BB), 256>>>();
    scan_pass2<<<dim3(DHH / 256, BB), 256>>>();
    scan_pass3<<<dim3(DHH / 256, NCHUNK, BB), 256>>>(hlast);

    // GEMM2: y = y_pre @ Wo + bo
    gemm_kernel<DMM, 1><<<dim3(DMM / 128, MMT / 128), 256>>>(nullptr, Wo, bo, y);
}

// round 2
// speedup vs baseline: 2.5750x; 2.5750x over previous
#include <cuda_runtime.h>
#include <math.h>
#include <stdint.h>

// Problem constants
#define BB   4
#define SS   4096
#define DMM  1024
#define DHH  1024
#define MMT  (BB*SS)      // 16384 rows
#define N1   (3*DHH)      // 3072
#define KK   1024

#define NCHUNK 128
#define TCH    (SS/NCHUNK)   // 32

// Scratch (device globals: allocation-free, graph-safe)
__device__ float g_tinp[(size_t)MMT*DHH];   // tanh(u0)
__device__ float g_gin [(size_t)MMT*DHH];   // sigmoid(u1) = input gate
__device__ float g_gout[(size_t)MMT*DHH];   // sigmoid(u2) = output gate
__device__ float g_ypre[(size_t)MMT*DHH];   // tanh(h)*og  (input to GEMM2)
__device__ float g_Ac [(size_t)BB*NCHUNK*DHH];
__device__ float g_Kc [(size_t)BB*NCHUNK*DHH];
__device__ float g_pref[(size_t)BB*NCHUNK*DHH];

// ---------------------------------------------------------------------------
// Helpers
// ---------------------------------------------------------------------------
__device__ __forceinline__ void cp_async16(void* smem_dst, const void* gsrc) {
    uint32_t s = (uint32_t)__cvta_generic_to_shared(smem_dst);
    asm volatile("cp.async.cg.shared.global [%0], [%1], 16;\n" :: "r"(s), "l"(gsrc));
}
__device__ __forceinline__ uint32_t f2tf(float f) {
    uint32_t r;
    asm("cvt.rna.tf32.f32 %0, %1;\n" : "=r"(r) : "f"(f));
    return r;
}
__device__ __forceinline__ void mma_tf32(float* d, const uint32_t* a, const uint32_t* b) {
    asm volatile(
        "mma.sync.aligned.m16n8k8.row.col.f32.tf32.tf32.f32 "
        "{%0,%1,%2,%3}, {%4,%5,%6,%7}, {%8,%9}, {%0,%1,%2,%3};\n"
        : "+f"(d[0]), "+f"(d[1]), "+f"(d[2]), "+f"(d[3])
        : "r"(a[0]), "r"(a[1]), "r"(a[2]), "r"(a[3]), "r"(b[0]), "r"(b[1]));
}

// ---------------------------------------------------------------------------
// tf32 tensor-core GEMM: C[M,NN] = A[M,1024] * B[1024,NN] (+bias)
// BM=128 BN=128 BK=32, 256 threads (8 warps, 2Mx4N), warp tile 64x32.
// cp.async 2-stage double buffer.
// SMEM layouts (floats): As[m][36] (row pad -> frag LDS conflict-free),
//                        Bs[k][136].
// MODE 0: GEMM1 epilogue -> split activations into g_tinp/g_gin/g_gout
// MODE 1: GEMM2 epilogue -> Cout = acc + bias, A source is g_ypre
// ---------------------------------------------------------------------------
#define BM 128
#define BN 128
#define BKG 32
#define ASZ (BM*36)       // 4608 floats
#define BSZ (BKG*136)     // 4352 floats
#define STG (ASZ+BSZ)     // 8960 floats per stage

template<int NN, int MODE>
__global__ __launch_bounds__(256)
void gemm_tc(const float* __restrict__ Ain,
             const float* __restrict__ Bmat,
             const float* __restrict__ bias,
             float* __restrict__ Cout)
{
    extern __shared__ float sm[];
    const float* A = (MODE == 1) ? g_ypre : Ain;

    const int tid  = threadIdx.x;
    const int n0   = blockIdx.x * BN;
    const int m0   = blockIdx.y * BM;
    const int warp = tid >> 5;
    const int lane = tid & 31;
    const int qid  = lane >> 2;     // 0..7
    const int tq   = lane & 3;      // 0..3
    const int wm   = (warp & 1) * 64;
    const int wn   = (warp >> 1) * 32;

    float acc[4][4][4];
#pragma unroll
    for (int mi = 0; mi < 4; mi++)
#pragma unroll
        for (int ni = 0; ni < 4; ni++)
#pragma unroll
            for (int r = 0; r < 4; r++) acc[mi][ni][r] = 0.f;

    // stage loader
    auto load_stage = [&](int st, int k0) {
        float* As = sm + st * STG;
        float* Bs = sm + st * STG + ASZ;
#pragma unroll
        for (int i = 0; i < 4; i++) {
            int idx = tid + i * 256;          // 0..1023
            int r   = idx >> 3;               // 0..127
            int c4  = idx & 7;                // 0..7
            cp_async16(As + r * 36 + c4 * 4,
                       A + (size_t)(m0 + r) * KK + k0 + c4 * 4);
        }
#pragma unroll
        for (int i = 0; i < 4; i++) {
            int idx = tid + i * 256;
            int r   = idx >> 5;               // 0..31
            int c4  = idx & 31;               // 0..31
            cp_async16(Bs + r * 136 + c4 * 4,
                       Bmat + (size_t)(k0 + r) * NN + n0 + c4 * 4);
        }
        asm volatile("cp.async.commit_group;\n");
    };

    load_stage(0, 0);
    int st = 0;
    for (int k0 = 0; k0 < KK; k0 += BKG) {
        bool more = (k0 + BKG < KK);
        if (more) {
            load_stage(st ^ 1, k0 + BKG);
            asm volatile("cp.async.wait_group 1;\n");
        } else {
            asm volatile("cp.async.wait_group 0;\n");
        }
        __syncthreads();

        const float* As = sm + st * STG;
        const float* Bs = sm + st * STG + ASZ;

#pragma unroll
        for (int kk = 0; kk < BKG; kk += 8) {
            uint32_t af[4][4], bf[4][2];
#pragma unroll
            for (int mi = 0; mi < 4; mi++) {
                const float* ap = As + (wm + mi * 16 + qid) * 36 + kk + tq;
                af[mi][0] = f2tf(ap[0]);
                af[mi][2] = f2tf(ap[4]);
                af[mi][1] = f2tf(ap[8 * 36]);
                af[mi][3] = f2tf(ap[8 * 36 + 4]);
            }
#pragma unroll
            for (int ni = 0; ni < 4; ni++) {
                const float* bp = Bs + (kk + tq) * 136 + wn + ni * 8 + qid;
                bf[ni][0] = f2tf(bp[0]);
                bf[ni][1] = f2tf(bp[4 * 136]);
            }
#pragma unroll
            for (int mi = 0; mi < 4; mi++)
#pragma unroll
                for (int ni = 0; ni < 4; ni++)
                    mma_tf32(acc[mi][ni], af[mi], bf[ni]);
        }
        __syncthreads();
        st ^= 1;
    }

    // Epilogue. c0,c1 -> row qid, cols 2tq,2tq+1 ; c2,c3 -> row qid+8
#pragma unroll
    for (int mi = 0; mi < 4; mi++) {
#pragma unroll
        for (int ni = 0; ni < 4; ni++) {
            int colb = n0 + wn + ni * 8 + 2 * tq;
#pragma unroll
            for (int h = 0; h < 2; h++) {
                int row = m0 + wm + mi * 16 + qid + h * 8;
#pragma unroll
                for (int w = 0; w < 2; w++) {
                    int col = colb + w;
                    float u = acc[mi][ni][h * 2 + w] + bias[col];
                    if (MODE == 0) {
                        int third = col >> 10;
                        size_t o = (size_t)row * DHH + (col & 1023);
                        if (third == 0)      g_tinp[o] = tanhf(u);
                        else if (third == 1) g_gin[o]  = 1.f / (1.f + expf(-u));
                        else                 g_gout[o] = 1.f / (1.f + expf(-u));
                    } else {
                        Cout[(size_t)row * NN + col] = u;
                    }
                }
            }
        }
    }
}

// ---------------------------------------------------------------------------
// Scan pass 1: per-chunk aggregates. Each thread owns 4 channels (float4).
// grid (NCHUNK, BB), block 256 (256*4 = 1024 channels)
// ---------------------------------------------------------------------------
__global__ __launch_bounds__(256)
void scan_pass1()
{
    int c     = threadIdx.x * 4;
    int chunk = blockIdx.x;
    int b     = blockIdx.y;
    size_t base = ((size_t)b * SS + (size_t)chunk * TCH) * DHH + c;

    float Af[4] = {1.f, 1.f, 1.f, 1.f};
    float Kf[4] = {0.f, 0.f, 0.f, 0.f};
#pragma unroll 4
    for (int t = 0; t < TCH; t++) {
        size_t idx = base + (size_t)t * DHH;
        float4 gi = *reinterpret_cast<const float4*>(&g_gin[idx]);
        float4 ti = *reinterpret_cast<const float4*>(&g_tinp[idx]);
        float g[4] = {gi.x, gi.y, gi.z, gi.w};
        float tt[4] = {ti.x, ti.y, ti.z, ti.w};
#pragma unroll
        for (int j = 0; j < 4; j++) {
            float f = 1.f - g[j];
            Kf[j] = fmaf(f, Kf[j], tt[j] * g[j]);
            Af[j] *= f;
        }
    }
    size_t o = ((size_t)b * NCHUNK + chunk) * DHH + c;
    *reinterpret_cast<float4*>(&g_Ac[o]) = make_float4(Af[0], Af[1], Af[2], Af[3]);
    *reinterpret_cast<float4*>(&g_Kc[o]) = make_float4(Kf[0], Kf[1], Kf[2], Kf[3]);
}

// ---------------------------------------------------------------------------
// Scan pass 2: sequential scan over chunk aggregates. grid (BB), block 256.
// ---------------------------------------------------------------------------
__global__ __launch_bounds__(256)
void scan_pass2()
{
    int c = threadIdx.x * 4;
    int b = blockIdx.x;
    float carry[4] = {0.f, 0.f, 0.f, 0.f};
#pragma unroll 8
    for (int j = 0; j < NCHUNK; j++) {
        size_t o = ((size_t)b * NCHUNK + j) * DHH + c;
        float4 Ac = *reinterpret_cast<const float4*>(&g_Ac[o]);
        float4 Kc = *reinterpret_cast<const float4*>(&g_Kc[o]);
        *reinterpret_cast<float4*>(&g_pref[o]) =
            make_float4(carry[0], carry[1], carry[2], carry[3]);
        carry[0] = fmaf(Ac.x, carry[0], Kc.x);
        carry[1] = fmaf(Ac.y, carry[1], Kc.y);
        carry[2] = fmaf(Ac.z, carry[2], Kc.z);
        carry[3] = fmaf(Ac.w, carry[3], Kc.w);
    }
}

// ---------------------------------------------------------------------------
// Scan pass 3: replay chunks with prefix; emit y_pre and h_last.
// grid (NCHUNK, BB), block 256.
// ---------------------------------------------------------------------------
__global__ __launch_bounds__(256)
void scan_pass3(float* __restrict__ hlast)
{
    int c     = threadIdx.x * 4;
    int chunk = blockIdx.x;
    int b     = blockIdx.y;

    size_t po = ((size_t)b * NCHUNK + chunk) * DHH + c;
    float4 pr = *reinterpret_cast<const float4*>(&g_pref[po]);
    float h[4] = {pr.x, pr.y, pr.z, pr.w};

    size_t base = ((size_t)b * SS + (size_t)chunk * TCH) * DHH + c;
#pragma unroll 2
    for (int t = 0; t < TCH; t++) {
        size_t idx = base + (size_t)t * DHH;
        float4 gi = *reinterpret_cast<const float4*>(&g_gin[idx]);
        float4 ti = *reinterpret_cast<const float4*>(&g_tinp[idx]);
        float4 go = *reinterpret_cast<const float4*>(&g_gout[idx]);
        float g[4] = {gi.x, gi.y, gi.z, gi.w};
        float tt[4] = {ti.x, ti.y, ti.z, ti.w};
        float og[4] = {go.x, go.y, go.z, go.w};
        float yp[4];
#pragma unroll
        for (int j = 0; j < 4; j++) {
            float f = 1.f - g[j];
            h[j] = fmaf(f, h[j], tt[j] * g[j]);
            yp[j] = tanhf(h[j]) * og[j];
        }
        *reinterpret_cast<float4*>(&g_ypre[idx]) =
            make_float4(yp[0], yp[1], yp[2], yp[3]);
    }
    if (chunk == NCHUNK - 1) {
        *reinterpret_cast<float4*>(&hlast[(size_t)b * DHH + c]) =
            make_float4(h[0], h[1], h[2], h[3]);
    }
}

// ---------------------------------------------------------------------------
extern "C" void kernel_launch(void* const* d_in, const int* in_sizes, int n_in,
                              void* d_out, int out_size)
{
    const float* x  = (const float*)d_in[0];   // (4,4096,1024)
    const float* Wp = (const float*)d_in[1];   // (1024,3072)
    const float* bp = (const float*)d_in[2];   // (3072,)
    const float* Wo = (const float*)d_in[3];   // (1024,1024)
    const float* bo = (const float*)d_in[4];   // (1024,)

    float* out   = (float*)d_out;
    float* hlast = out;                         // (4,1024)
    float* y     = out + (size_t)BB * DHH;      // (4,4096,1024)

    const int smem_bytes = 2 * STG * sizeof(float);   // 71680 B
    cudaFuncSetAttribute(gemm_tc<N1, 0>,
                         cudaFuncAttributeMaxDynamicSharedMemorySize, smem_bytes);
    cudaFuncSetAttribute(gemm_tc<DMM, 1>,
                         cudaFuncAttributeMaxDynamicSharedMemorySize, smem_bytes);

    // GEMM1: u = x @ Wp + bp, fused activation split
    gemm_tc<N1, 0><<<dim3(N1 / BN, MMT / BM), 256, smem_bytes>>>(x, Wp, bp, nullptr);

    // Chunked linear-recurrence scan
    scan_pass1<<<dim3(NCHUNK, BB), 256>>>();
    scan_pass2<<<BB, 256>>>();
    scan_pass3<<<dim3(NCHUNK, BB), 256>>>(hlast);

    // GEMM2: y = y_pre @ Wo + bo
    gemm_tc<DMM, 1><<<dim3(DMM / BN, MMT / BM), 256, smem_bytes>>>(nullptr, Wo, bo, y);
}